// round 9
// baseline (speedup 1.0000x reference)
#include <cuda_runtime.h>
#include <cuda_bf16.h>

// CollisionRegularizer: mean over (B,N,N) of relu(R - dist)^2, diagonal masked.
// B=2, N=8192, xyz float32 (B,N,3). Output: 1 float (the mean).
//
// R5: spatial binning. Pairs with dist >= R contribute exactly 0, and with a
// cell size of R=0.1 (10x10x10 grid) every pair with dist < R lies within the
// 27-cell neighborhood. Candidate pairs: 67M -> ~3.6M (exact result, the
// skipped pairs are exact zeros).
//
// Pipeline (all graph-capturable, zero allocations):
//  K1 count:   cell id per point + per-cell histogram (atomics).
//  K2 scan:    exclusive scan -> cell starts + scatter cursors; zeroes counts
//              for the next replay.
//  K3 scatter: counting-sort points into SoA arrays (atomic rank).
//  K4 sort:    per-cell insertion sort by original index -> deterministic
//              list order despite nondeterministic atomic scatter.
//  K5 main:    block per (batch, cell); gather 27-neighborhood (9 contiguous
//              x-runs) to shared; direct-difference distances; self-pair
//              contributes exactly R^2 via sqrt.approx(0)=0, subtracted
//              analytically; fused last-block fixed-order reduction.

#define RADIUS  0.1f
#define NPTS    8192
#define NBATCH  2
#define GRES    10
#define NCELLS  (GRES * GRES * GRES)      // 1000
#define NBLK    (NBATCH * NCELLS)         // 2000 main blocks / partials
#define MAXCAND 768                       // >> worst-case 27-cell population
#define MTHREADS 128

__device__ int   g_count[NBATCH][NCELLS];
__device__ int   g_start[NBATCH][NCELLS + 1];
__device__ int   g_cursor[NBATCH][NCELLS];
__device__ int   g_cell[NBATCH][NPTS];
__device__ float g_px[NBATCH][NPTS];
__device__ float g_py[NBATCH][NPTS];
__device__ float g_pz[NBATCH][NPTS];
__device__ int   g_oidx[NBATCH][NPTS];
__device__ float g_part[NBLK];
__device__ unsigned int g_done = 0;

__device__ __forceinline__ float sqrt_approx(float x) {
    float r; asm("sqrt.approx.f32 %0, %1;" : "=f"(r) : "f"(x)); return r;
}
// t = R - d as FFMA with immediate multiplier (-1.0f).
__device__ __forceinline__ float r_minus(float d, float R) {
    float r; asm("fma.rn.f32 %0, %1, 0fBF800000, %2;" : "=f"(r) : "f"(d), "f"(R)); return r;
}

// ---- K1: cell ids + histogram -------------------------------------------
__global__ void count_kernel(const float* __restrict__ xyz) {
    const int t = blockIdx.x * blockDim.x + threadIdx.x;
    if (t >= NBATCH * NPTS) return;
    const int b = t / NPTS, n = t % NPTS;
    const float* p = xyz + ((size_t)b * NPTS + n) * 3;
    const int cx = min((int)(p[0] * (float)GRES), GRES - 1);
    const int cy = min((int)(p[1] * (float)GRES), GRES - 1);
    const int cz = min((int)(p[2] * (float)GRES), GRES - 1);
    const int c  = cx + GRES * cy + GRES * GRES * cz;
    g_cell[b][n] = c;
    atomicAdd(&g_count[b][c], 1);
}

// ---- K2: exclusive scan per batch (single block, 1024 threads) ----------
__global__ void scan_kernel() {
    __shared__ int s[1024];
    const int tid = threadIdx.x;
    for (int b = 0; b < NBATCH; b++) {
        const int v = (tid < NCELLS) ? g_count[b][tid] : 0;
        s[tid] = v;
        __syncthreads();
        // Hillis-Steele inclusive scan.
        for (int off = 1; off < 1024; off <<= 1) {
            const int t = (tid >= off) ? s[tid - off] : 0;
            __syncthreads();
            s[tid] += t;
            __syncthreads();
        }
        if (tid < NCELLS) {
            const int excl = s[tid] - v;
            g_start[b][tid]  = excl;
            g_cursor[b][tid] = excl;
            if (tid == NCELLS - 1) g_start[b][NCELLS] = s[tid];
            g_count[b][tid] = 0;   // reset for next graph replay
        }
        __syncthreads();
    }
}

// ---- K3: counting-sort scatter ------------------------------------------
__global__ void scatter_kernel(const float* __restrict__ xyz) {
    const int t = blockIdx.x * blockDim.x + threadIdx.x;
    if (t >= NBATCH * NPTS) return;
    const int b = t / NPTS, n = t % NPTS;
    const float* p = xyz + ((size_t)b * NPTS + n) * 3;
    const int c = g_cell[b][n];
    const int pos = atomicAdd(&g_cursor[b][c], 1);
    g_px[b][pos] = p[0];
    g_py[b][pos] = p[1];
    g_pz[b][pos] = p[2];
    g_oidx[b][pos] = n;
}

// ---- K4: per-cell sort by original index (determinism fixup) ------------
__global__ void cellsort_kernel() {
    const int t = blockIdx.x * blockDim.x + threadIdx.x;
    if (t >= NBLK) return;
    const int b = t / NCELLS, c = t % NCELLS;
    const int s0 = g_start[b][c], s1 = g_start[b][c + 1];
    for (int i = s0 + 1; i < s1; i++) {
        const int   key = g_oidx[b][i];
        const float x = g_px[b][i], y = g_py[b][i], z = g_pz[b][i];
        int j = i - 1;
        while (j >= s0 && g_oidx[b][j] > key) {
            g_oidx[b][j + 1] = g_oidx[b][j];
            g_px[b][j + 1] = g_px[b][j];
            g_py[b][j + 1] = g_py[b][j];
            g_pz[b][j + 1] = g_pz[b][j];
            j--;
        }
        g_oidx[b][j + 1] = key;
        g_px[b][j + 1] = x; g_py[b][j + 1] = y; g_pz[b][j + 1] = z;
    }
}

// ---- K5: neighborhood evaluation + fused reduction ----------------------
__global__ __launch_bounds__(MTHREADS)
void main_kernel(float* __restrict__ out) {
    __shared__ __align__(16) float sx[MAXCAND];
    __shared__ __align__(16) float sy[MAXCAND];
    __shared__ __align__(16) float sz[MAXCAND];
    __shared__ float red[MTHREADS];
    __shared__ bool  is_last;

    const int tid = threadIdx.x;
    const int blk = blockIdx.x;
    const int b = blk / NCELLS, c = blk % NCELLS;
    const int cx = c % GRES, cy = (c / GRES) % GRES, cz = c / (GRES * GRES);

    // Gather the 27-cell neighborhood: 9 contiguous x-runs.
    int ncand = 0;   // computed uniformly by all threads
    for (int dz = -1; dz <= 1; dz++) {
        const int nz = cz + dz;
        if (nz < 0 || nz >= GRES) continue;
        for (int dy = -1; dy <= 1; dy++) {
            const int ny = cy + dy;
            if (ny < 0 || ny >= GRES) continue;
            const int x0 = max(cx - 1, 0), x1 = min(cx + 1, GRES - 1);
            const int cbase = GRES * ny + GRES * GRES * nz;
            const int src0 = g_start[b][x0 + cbase];
            const int src1 = g_start[b][x1 + cbase + 1];
            int len = src1 - src0;
            if (len > MAXCAND - ncand) len = MAXCAND - ncand;  // safety clamp
            for (int k = tid; k < len; k += MTHREADS) {
                sx[ncand + k] = g_px[b][src0 + k];
                sy[ncand + k] = g_py[b][src0 + k];
                sz[ncand + k] = g_pz[b][src0 + k];
            }
            ncand += len;
        }
    }
    __syncthreads();

    const float R = RADIUS;
    const int i0 = g_start[b][c], i1 = g_start[b][c + 1];
    float acc = 0.0f;
    for (int ii = i0; ii < i1; ii++) {
        const float xi = g_px[b][ii];   // broadcast loads (L1-resident)
        const float yi = g_py[b][ii];
        const float zi = g_pz[b][ii];
        for (int jj = tid; jj < ncand; jj += MTHREADS) {
            const float dx = xi - sx[jj];
            const float dy = yi - sy[jj];
            const float dz = zi - sz[jj];
            float sq = dx * dx;
            sq = fmaf(dy, dy, sq);
            sq = fmaf(dz, dz, sq);
            // Self-pair: sq is exactly 0 -> contributes exactly R^2
            // (subtracted analytically at the end).
            const float d  = sqrt_approx(sq);
            const float tt = fmaxf(r_minus(d, R), 0.0f);
            acc = fmaf(tt, tt, acc);
        }
    }

    // Fixed-order block reduction.
    red[tid] = acc;
    __syncthreads();
#pragma unroll
    for (int s = MTHREADS / 2; s > 0; s >>= 1) {
        if (tid < s) red[tid] += red[tid + s];
        __syncthreads();
    }

    if (tid == 0) {
        g_part[blk] = red[0];
        __threadfence();
        const unsigned int p = atomicAdd(&g_done, 1u);
        is_last = (p == NBLK - 1);
    }
    __syncthreads();

    // Last block: fixed-order final reduction (deterministic regardless of
    // which block runs it).
    if (is_last) {
        if (tid == 0) g_done = 0;   // reset for next graph replay
        __threadfence();
        const volatile float* gp = g_part;
        float v = 0.0f;
        for (int i = tid; i < NBLK; i += MTHREADS) v += gp[i];
        red[tid] = v;
        __syncthreads();
#pragma unroll
        for (int s = MTHREADS / 2; s > 0; s >>= 1) {
            if (tid < s) red[tid] += red[tid + s];
            __syncthreads();
        }
        if (tid == 0) {
            const float diag = (float)(NBATCH * NPTS) * (RADIUS * RADIUS);
            out[0] = (red[0] - diag) /
                     ((float)NBATCH * (float)NPTS * (float)NPTS);
        }
    }
}

extern "C" void kernel_launch(void* const* d_in, const int* in_sizes, int n_in,
                              void* d_out, int out_size) {
    const float* xyz = (const float*)d_in[0];
    float* out = (float*)d_out;
    (void)in_sizes; (void)n_in; (void)out_size;

    const int npt = NBATCH * NPTS;
    count_kernel  <<<(npt + 511) / 512, 512>>>(xyz);
    scan_kernel   <<<1, 1024>>>();
    scatter_kernel<<<(npt + 511) / 512, 512>>>(xyz);
    cellsort_kernel<<<(NBLK + 255) / 256, 256>>>();
    main_kernel   <<<NBLK, MTHREADS>>>(out);
}

// round 10
// speedup vs baseline: 1.0642x; 1.0642x over previous
#include <cuda_runtime.h>
#include <cuda_bf16.h>

// CollisionRegularizer: mean over (B,N,N) of relu(R - dist)^2, diagonal masked.
// B=2, N=8192, xyz float32 (B,N,3). Output: 1 float (the mean).
//
// R6: spatial binning with DETERMINISTIC scatter (no per-cell sort — R5's
// 33.7us cellsort is deleted). Rank of a point within its cell is computed
// arithmetically: per-(segment,cell) histograms (atomic counts only —
// order-independent) + in-segment shared-memory rank scan. Every scatter
// position is a pure function of the input.
//
//  K1 count+rank: cell id, seg histogram, rank-in-segment via shared scan.
//  K2 scan:       per-cell prefix over segments + cell scan -> starts/offsets
//                 (also zeroes histograms for the next graph replay).
//  K3 scatter:    pos = segoff[seg][cell] + rank (no atomics).
//  K5 main:       block per (batch,cell); 27-neighborhood (9 contiguous
//                 x-runs) to shared; self-pair contributes exactly R^2 via
//                 sqrt.approx(0)=0, subtracted analytically; fused last-block
//                 fixed-order reduction.

#define RADIUS  0.1f
#define NPTS    8192
#define NBATCH  2
#define GRES    10
#define NCELLS  (GRES * GRES * GRES)      // 1000
#define SEG     256
#define NSEG    (NPTS / SEG)              // 32 segments per batch
#define NBLK    (NBATCH * NCELLS)         // 2000 main blocks / partials
#define MAXCAND 768
#define MTHREADS 128

__device__ int   g_segcnt[NBATCH][NSEG][NCELLS];
__device__ int   g_segoff[NBATCH][NSEG][NCELLS];
__device__ int   g_start[NBATCH][NCELLS + 1];
__device__ int   g_cell[NBATCH][NPTS];
__device__ int   g_rank[NBATCH][NPTS];
__device__ float g_px[NBATCH][NPTS];
__device__ float g_py[NBATCH][NPTS];
__device__ float g_pz[NBATCH][NPTS];
__device__ float g_part[NBLK];
__device__ unsigned int g_done = 0;

__device__ __forceinline__ float sqrt_approx(float x) {
    float r; asm("sqrt.approx.f32 %0, %1;" : "=f"(r) : "f"(x)); return r;
}
__device__ __forceinline__ float r_minus(float d, float R) {
    float r; asm("fma.rn.f32 %0, %1, 0fBF800000, %2;" : "=f"(r) : "f"(d), "f"(R)); return r;
}

// ---- K1: cell id + segment histogram + deterministic rank-in-segment ----
__global__ __launch_bounds__(SEG)
void count_rank_kernel(const float* __restrict__ xyz) {
    __shared__ int scell[SEG];
    const int tid = threadIdx.x;
    const int b   = blockIdx.x / NSEG;
    const int sg  = blockIdx.x % NSEG;
    const int n   = sg * SEG + tid;

    const float* p = xyz + ((size_t)b * NPTS + n) * 3;
    const int cx = min((int)(p[0] * (float)GRES), GRES - 1);
    const int cy = min((int)(p[1] * (float)GRES), GRES - 1);
    const int cz = min((int)(p[2] * (float)GRES), GRES - 1);
    const int c  = cx + GRES * cy + GRES * GRES * cz;

    scell[tid] = c;
    atomicAdd(&g_segcnt[b][sg][c], 1);   // count only: order-independent
    __syncthreads();

    int rank = 0;
    for (int k = 0; k < tid; k++) rank += (scell[k] == c);

    g_cell[b][n] = c;
    g_rank[b][n] = rank;
}

// ---- K2: per-cell segment prefix + cell scan (single block) -------------
__global__ void scan_kernel() {
    __shared__ int s[1024];
    const int tid = threadIdx.x;
    for (int b = 0; b < NBATCH; b++) {
        int total = 0;
        if (tid < NCELLS) {
            for (int sg = 0; sg < NSEG; sg++) {
                g_segoff[b][sg][tid] = total;        // prefix within cell
                total += g_segcnt[b][sg][tid];
                g_segcnt[b][sg][tid] = 0;            // reset for replay
            }
        }
        s[tid] = (tid < NCELLS) ? total : 0;
        __syncthreads();
        for (int off = 1; off < 1024; off <<= 1) {   // inclusive scan
            const int t = (tid >= off) ? s[tid - off] : 0;
            __syncthreads();
            s[tid] += t;
            __syncthreads();
        }
        if (tid < NCELLS) {
            const int excl = s[tid] - total;
            g_start[b][tid] = excl;
            if (tid == NCELLS - 1) g_start[b][NCELLS] = s[tid];
            for (int sg = 0; sg < NSEG; sg++)
                g_segoff[b][sg][tid] += excl;        // absolute offsets
        }
        __syncthreads();
    }
}

// ---- K3: deterministic scatter (no atomics) -----------------------------
__global__ void scatter_kernel(const float* __restrict__ xyz) {
    const int t = blockIdx.x * blockDim.x + threadIdx.x;
    if (t >= NBATCH * NPTS) return;
    const int b = t / NPTS, n = t % NPTS;
    const int sg = n / SEG;
    const int c  = g_cell[b][n];
    const int pos = g_segoff[b][sg][c] + g_rank[b][n];
    const float* p = xyz + ((size_t)b * NPTS + n) * 3;
    g_px[b][pos] = p[0];
    g_py[b][pos] = p[1];
    g_pz[b][pos] = p[2];
}

// ---- K5: neighborhood evaluation + fused reduction ----------------------
__global__ __launch_bounds__(MTHREADS)
void main_kernel(float* __restrict__ out) {
    __shared__ __align__(16) float sx[MAXCAND];
    __shared__ __align__(16) float sy[MAXCAND];
    __shared__ __align__(16) float sz[MAXCAND];
    __shared__ float red[MTHREADS];
    __shared__ bool  is_last;

    const int tid = threadIdx.x;
    const int blk = blockIdx.x;
    const int b = blk / NCELLS, c = blk % NCELLS;
    const int cx = c % GRES, cy = (c / GRES) % GRES, cz = c / (GRES * GRES);

    // Gather the 27-cell neighborhood as 9 contiguous x-runs.
    int ncand = 0;   // uniform across threads
    for (int dz = -1; dz <= 1; dz++) {
        const int nz = cz + dz;
        if (nz < 0 || nz >= GRES) continue;
        for (int dy = -1; dy <= 1; dy++) {
            const int ny = cy + dy;
            if (ny < 0 || ny >= GRES) continue;
            const int x0 = max(cx - 1, 0), x1 = min(cx + 1, GRES - 1);
            const int cbase = GRES * ny + GRES * GRES * nz;
            const int src0 = g_start[b][x0 + cbase];
            const int src1 = g_start[b][x1 + cbase + 1];
            int len = src1 - src0;
            if (len > MAXCAND - ncand) len = MAXCAND - ncand;  // safety
            for (int k = tid; k < len; k += MTHREADS) {
                sx[ncand + k] = g_px[b][src0 + k];
                sy[ncand + k] = g_py[b][src0 + k];
                sz[ncand + k] = g_pz[b][src0 + k];
            }
            ncand += len;
        }
    }
    __syncthreads();

    const float R = RADIUS;
    const int i0 = g_start[b][c], i1 = g_start[b][c + 1];
    float acc = 0.0f;
    for (int ii = i0; ii < i1; ii++) {
        const float xi = g_px[b][ii];
        const float yi = g_py[b][ii];
        const float zi = g_pz[b][ii];
        for (int jj = tid; jj < ncand; jj += MTHREADS) {
            const float dx = xi - sx[jj];
            const float dy = yi - sy[jj];
            const float dz = zi - sz[jj];
            float sq = dx * dx;
            sq = fmaf(dy, dy, sq);
            sq = fmaf(dz, dz, sq);
            const float d  = sqrt_approx(sq);     // self-pair: sqrt(0)=0 -> R^2
            const float tt = fmaxf(r_minus(d, R), 0.0f);
            acc = fmaf(tt, tt, acc);
        }
    }

    red[tid] = acc;
    __syncthreads();
#pragma unroll
    for (int s = MTHREADS / 2; s > 0; s >>= 1) {
        if (tid < s) red[tid] += red[tid + s];
        __syncthreads();
    }

    if (tid == 0) {
        g_part[blk] = red[0];
        __threadfence();
        const unsigned int p = atomicAdd(&g_done, 1u);
        is_last = (p == NBLK - 1);
    }
    __syncthreads();

    // Last block: fixed-order final reduction.
    if (is_last) {
        if (tid == 0) g_done = 0;
        __threadfence();
        const volatile float* gp = g_part;
        float v = 0.0f;
        for (int i = tid; i < NBLK; i += MTHREADS) v += gp[i];
        red[tid] = v;
        __syncthreads();
#pragma unroll
        for (int s = MTHREADS / 2; s > 0; s >>= 1) {
            if (tid < s) red[tid] += red[tid + s];
            __syncthreads();
        }
        if (tid == 0) {
            const float diag = (float)(NBATCH * NPTS) * (RADIUS * RADIUS);
            out[0] = (red[0] - diag) /
                     ((float)NBATCH * (float)NPTS * (float)NPTS);
        }
    }
}

extern "C" void kernel_launch(void* const* d_in, const int* in_sizes, int n_in,
                              void* d_out, int out_size) {
    const float* xyz = (const float*)d_in[0];
    float* out = (float*)d_out;
    (void)in_sizes; (void)n_in; (void)out_size;

    const int npt = NBATCH * NPTS;
    count_rank_kernel<<<NBATCH * NSEG, SEG>>>(xyz);
    scan_kernel      <<<1, 1024>>>();
    scatter_kernel   <<<(npt + 511) / 512, 512>>>(xyz);
    main_kernel      <<<NBLK, MTHREADS>>>(out);
}

// round 11
// speedup vs baseline: 1.7103x; 1.6071x over previous
#include <cuda_runtime.h>
#include <cuda_bf16.h>

// CollisionRegularizer: mean over (B,N,N) of relu(R - dist)^2, diagonal masked.
// B=2, N=8192, xyz float32 (B,N,3). Output: 1 float (the mean).
//
// R7: ONE persistent kernel (grid = 148 blocks, co-resident) with internal
// grid barriers. All of R6's prep kernels become phases; main phase is
// warp-per-cell with lane-parallel neighborhood bounds. Deterministic
// throughout (atomics only on integer counts / barrier words; all float
// sums in fixed order).

#define RADIUS  0.1f
#define NPTS    8192
#define NBATCH  2
#define GRES    10
#define NCELLS  (GRES * GRES * GRES)          // 1000
#define SEG     256
#define NSEG    (NPTS / SEG)                  // 32 segments per batch
#define NSEGT   (NBATCH * NSEG)               // 64 total segments
#define GRID    148
#define BTHREADS 256
#define NWARPS  (GRID * (BTHREADS / 32))      // 1184 warps
#define NCELLT  (NBATCH * NCELLS)             // 2000 cells total
#define CAP     64                            // staged points per cell (P>~1e-30 overflow)

__device__ int   g_segcnt[NBATCH][NSEG][NCELLS];
__device__ int   g_segoff[NBATCH][NSEG][NCELLS];   // within-cell prefix
__device__ int   g_ctot[NBATCH][NCELLS];
__device__ int   g_start[NBATCH][NCELLS + 1];
__device__ int   g_cell[NBATCH][NPTS];
__device__ int   g_rank[NBATCH][NPTS];
__device__ float g_px[NBATCH][NPTS];
__device__ float g_py[NBATCH][NPTS];
__device__ float g_pz[NBATCH][NPTS];
__device__ float g_part[GRID];

__device__ unsigned int          g_arrive  = 0;
__device__ volatile unsigned int g_release = 0;

__device__ __forceinline__ float sqrt_approx(float x) {
    float r; asm("sqrt.approx.f32 %0, %1;" : "=f"(r) : "f"(x)); return r;
}
__device__ __forceinline__ float r_minus(float d, float R) {
    float r; asm("fma.rn.f32 %0, %1, 0fBF800000, %2;" : "=f"(r) : "f"(d), "f"(R)); return r;
}

// Grid barrier, phase = 1,2,3,... All GRID blocks must be co-resident.
__device__ __forceinline__ void grid_barrier(unsigned int phase) {
    __syncthreads();
    if (threadIdx.x == 0) {
        __threadfence();
        const unsigned int t = atomicAdd(&g_arrive, 1u);
        if (t == phase * GRID - 1u) {
            g_release = phase;            // release store (fence above)
        } else {
            while (g_release < phase) __nanosleep(64);
        }
        __threadfence();                  // acquire
    }
    __syncthreads();
}

__global__ __launch_bounds__(BTHREADS)
void collreg_persistent(const float* __restrict__ xyz, float* __restrict__ out) {
    __shared__ union {
        struct { int scell[SEG]; int hist[NCELLS]; } p1;
        struct { int scan[BTHREADS]; } p2;
        struct { float wx[8][CAP]; float wy[8][CAP]; float wz[8][CAP]; float red[8]; } p4;
        struct { float red[BTHREADS]; } fin;
    } sm;

    const int tid  = threadIdx.x;
    const int blk  = blockIdx.x;
    const int wid  = tid / 32;
    const int lane = tid % 32;
    const int gt   = blk * BTHREADS + tid;

    // ---------------- P1: cell ids + ranks + segment histograms ----------
    if (blk < NSEGT) {
        const int b  = blk / NSEG;
        const int sg = blk % NSEG;
        const int n  = sg * SEG + tid;
        const float* p = xyz + ((size_t)b * NPTS + n) * 3;
        const int cx = min((int)(p[0] * (float)GRES), GRES - 1);
        const int cy = min((int)(p[1] * (float)GRES), GRES - 1);
        const int cz = min((int)(p[2] * (float)GRES), GRES - 1);
        const int c  = cx + GRES * cy + GRES * GRES * cz;

        sm.p1.scell[tid] = c;
        for (int i = tid; i < NCELLS; i += BTHREADS) sm.p1.hist[i] = 0;
        __syncthreads();

        atomicAdd(&sm.p1.hist[c], 1);     // order-independent count
        int rank = 0;
        for (int k = 0; k < tid; k++) rank += (sm.p1.scell[k] == c);
        __syncthreads();

        for (int i = tid; i < NCELLS; i += BTHREADS) g_segcnt[b][sg][i] = sm.p1.hist[i];
        g_cell[b][n] = c;
        g_rank[b][n] = rank;
    }
    grid_barrier(1);

    // ---------------- P2a: per-cell prefix over segments ------------------
    if (gt < NCELLT) {
        const int b = gt / NCELLS, c = gt % NCELLS;
        int run = 0;
#pragma unroll
        for (int sg = 0; sg < NSEG; sg++) {
            const int v = g_segcnt[b][sg][c];
            g_segoff[b][sg][c] = run;
            run += v;
            g_segcnt[b][sg][c] = 0;       // reset for next graph replay
        }
        g_ctot[b][c] = run;
    }
    grid_barrier(2);

    // ---------------- P2b: cell scan (block 0 only) -----------------------
    if (blk == 0) {
        for (int b = 0; b < NBATCH; b++) {
            const int bi = tid * 4;
            int v0 = (bi + 0 < NCELLS) ? g_ctot[b][bi + 0] : 0;
            int v1 = (bi + 1 < NCELLS) ? g_ctot[b][bi + 1] : 0;
            int v2 = (bi + 2 < NCELLS) ? g_ctot[b][bi + 2] : 0;
            int v3 = (bi + 3 < NCELLS) ? g_ctot[b][bi + 3] : 0;
            const int tot = v0 + v1 + v2 + v3;
            sm.p2.scan[tid] = tot;
            __syncthreads();
            for (int off = 1; off < BTHREADS; off <<= 1) {
                const int t2 = (tid >= off) ? sm.p2.scan[tid - off] : 0;
                __syncthreads();
                sm.p2.scan[tid] += t2;
                __syncthreads();
            }
            const int excl = sm.p2.scan[tid] - tot;
            if (bi + 0 < NCELLS) g_start[b][bi + 0] = excl;
            if (bi + 1 < NCELLS) g_start[b][bi + 1] = excl + v0;
            if (bi + 2 < NCELLS) g_start[b][bi + 2] = excl + v0 + v1;
            if (bi + 3 < NCELLS) g_start[b][bi + 3] = excl + v0 + v1 + v2;
            if (tid == BTHREADS - 1) g_start[b][NCELLS] = sm.p2.scan[tid];
            __syncthreads();
        }
    }
    grid_barrier(3);

    // ---------------- P3: deterministic scatter ---------------------------
    if (gt < NBATCH * NPTS) {
        const int b = gt / NPTS, n = gt % NPTS;
        const int sg = n / SEG;
        const int c  = g_cell[b][n];
        const int pos = g_start[b][c] + g_segoff[b][sg][c] + g_rank[b][n];
        const float* p = xyz + ((size_t)b * NPTS + n) * 3;
        g_px[b][pos] = p[0];
        g_py[b][pos] = p[1];
        g_pz[b][pos] = p[2];
    }
    grid_barrier(4);

    // ---------------- P4: warp-per-cell pair evaluation -------------------
    const float R = RADIUS;
    float wtot = 0.0f;
    for (int cell = blk * 8 + wid; cell < NCELLT; cell += NWARPS) {
        const int b = cell / NCELLS, c = cell % NCELLS;
        const int cx = c % GRES, cy = (c / GRES) % GRES, cz = c / (GRES * GRES);
        const int i0 = g_start[b][c];
        const int cnt = g_start[b][c + 1] - i0;
        const int scnt = min(cnt, CAP);

        for (int l = lane; l < scnt; l += 32) {
            sm.p4.wx[wid][l] = g_px[b][i0 + l];
            sm.p4.wy[wid][l] = g_py[b][i0 + l];
            sm.p4.wz[wid][l] = g_pz[b][i0 + l];
        }
        __syncwarp();

        // Lane r (< 9) computes bounds of x-run r of the 27-neighborhood.
        int s0 = 0, s1 = 0;
        if (lane < 9) {
            const int nz = cz + lane / 3 - 1;
            const int ny = cy + lane % 3 - 1;
            if (nz >= 0 && nz < GRES && ny >= 0 && ny < GRES) {
                const int x0 = max(cx - 1, 0), x1 = min(cx + 1, GRES - 1);
                const int cb = GRES * ny + GRES * GRES * nz;
                s0 = g_start[b][x0 + cb];
                s1 = g_start[b][x1 + cb + 1];
            }
        }

        float acc = 0.0f;
#pragma unroll
        for (int r = 0; r < 9; r++) {
            const int rs0 = __shfl_sync(0xFFFFFFFFu, s0, r);
            const int rs1 = __shfl_sync(0xFFFFFFFFu, s1, r);
            for (int jj = rs0 + lane; jj < rs1; jj += 32) {
                const float jx = g_px[b][jj];
                const float jy = g_py[b][jj];
                const float jz = g_pz[b][jj];
                for (int ii = 0; ii < scnt; ii++) {
                    const float dx = sm.p4.wx[wid][ii] - jx;
                    const float dy = sm.p4.wy[wid][ii] - jy;
                    const float dz = sm.p4.wz[wid][ii] - jz;
                    float sq = dx * dx;
                    sq = fmaf(dy, dy, sq);
                    sq = fmaf(dz, dz, sq);
                    const float d  = sqrt_approx(sq);   // self-pair -> exactly R^2
                    const float tt = fmaxf(r_minus(d, R), 0.0f);
                    acc = fmaf(tt, tt, acc);
                }
                // overflow path (cnt > CAP): astronomically rare, exact.
                for (int ii = CAP; ii < cnt; ii++) {
                    const float dx = g_px[b][i0 + ii] - jx;
                    const float dy = g_py[b][i0 + ii] - jy;
                    const float dz = g_pz[b][i0 + ii] - jz;
                    float sq = dx * dx;
                    sq = fmaf(dy, dy, sq);
                    sq = fmaf(dz, dz, sq);
                    const float d  = sqrt_approx(sq);
                    const float tt = fmaxf(r_minus(d, R), 0.0f);
                    acc = fmaf(tt, tt, acc);
                }
            }
        }
        // Deterministic warp butterfly reduction.
#pragma unroll
        for (int off = 16; off > 0; off >>= 1)
            acc += __shfl_xor_sync(0xFFFFFFFFu, acc, off);
        wtot += acc;
        __syncwarp();
    }

    if (lane == 0) sm.p4.red[wid] = wtot;
    __syncthreads();
    if (tid == 0) {
        float v = 0.0f;
#pragma unroll
        for (int w = 0; w < 8; w++) v += sm.p4.red[w];
        g_part[blk] = v;
    }
    grid_barrier(5);

    // ---------------- P5: final fixed-order reduction (block 0) -----------
    if (blk == 0) {
        sm.fin.red[tid] = (tid < GRID) ? g_part[tid] : 0.0f;
        __syncthreads();
#pragma unroll
        for (int s = BTHREADS / 2; s > 0; s >>= 1) {
            if (tid < s) sm.fin.red[tid] += sm.fin.red[tid + s];
            __syncthreads();
        }
        if (tid == 0) {
            const float diag = (float)(NBATCH * NPTS) * (RADIUS * RADIUS);
            out[0] = (sm.fin.red[0] - diag) /
                     ((float)NBATCH * (float)NPTS * (float)NPTS);
            g_arrive  = 0;    // reset barrier state for next graph replay
            g_release = 0;
        }
    }
}

extern "C" void kernel_launch(void* const* d_in, const int* in_sizes, int n_in,
                              void* d_out, int out_size) {
    const float* xyz = (const float*)d_in[0];
    float* out = (float*)d_out;
    (void)in_sizes; (void)n_in; (void)out_size;

    collreg_persistent<<<GRID, BTHREADS>>>(xyz, out);
}